// round 14
// baseline (speedup 1.0000x reference)
#include <cuda_runtime.h>
#include <cuda_fp16.h>
#include <cstdint>

// Problem constants (fixed shapes: N=2048, F=512, E=32)
#define FDIM 512
#define EDIM 32
#define NWARPS 8
#define NTHREADS (NWARPS * 32)
#define ROWH 40   // halves per FX row (80 B). 8-row ldmatrix groups span all 32 banks.
#define ROWB (ROWH * 2)

__device__ __forceinline__ float warpSum(float v) {
#pragma unroll
    for (int o = 16; o; o >>= 1) v += __shfl_xor_sync(0xffffffffu, v, o);
    return v;
}
__device__ __forceinline__ float ex2(float x) {   // 2^x (f32, epilogue only)
    float r;
    asm("ex2.approx.ftz.f32 %0, %1;" : "=f"(r) : "f"(x));
    return r;
}
__device__ __forceinline__ uint32_t ex2h2(uint32_t x) {   // 2^x on packed half2
    uint32_t r;
    asm("ex2.approx.f16x2 %0, %1;" : "=r"(r) : "r"(x));
    return r;
}
__device__ __forceinline__ uint32_t packh2(float lo, float hi) {
    __half2 h = __floats2half2_rn(lo, hi);
    return *(uint32_t*)&h;
}

__device__ __forceinline__ void ldmx4(uint32_t& r0, uint32_t& r1, uint32_t& r2, uint32_t& r3,
                                      uint32_t addr) {
    asm volatile("ldmatrix.sync.aligned.m8n8.x4.shared.b16 {%0,%1,%2,%3}, [%4];"
                 : "=r"(r0), "=r"(r1), "=r"(r2), "=r"(r3) : "r"(addr));
}
__device__ __forceinline__ void ldmx4t(uint32_t& r0, uint32_t& r1, uint32_t& r2, uint32_t& r3,
                                       uint32_t addr) {
    asm volatile("ldmatrix.sync.aligned.m8n8.x4.trans.shared.b16 {%0,%1,%2,%3}, [%4];"
                 : "=r"(r0), "=r"(r1), "=r"(r2), "=r"(r3) : "r"(addr));
}
__device__ __forceinline__ void mma16816(float& d0, float& d1, float& d2, float& d3,
                                         uint32_t a0, uint32_t a1, uint32_t a2, uint32_t a3,
                                         uint32_t b0, uint32_t b1) {
    asm volatile("mma.sync.aligned.m16n8k16.row.col.f32.f16.f16.f32 "
                 "{%0,%1,%2,%3},{%4,%5,%6,%7},{%8,%9},{%0,%1,%2,%3};"
                 : "+f"(d0), "+f"(d1), "+f"(d2), "+f"(d3)
                 : "r"(a0), "r"(a1), "r"(a2), "r"(a3), "r"(b0), "r"(b1));
}

// Shared layout:
//   FXh   : FDIM*ROWH halves = 40960 B   compacted FX (fp16), 40-half row stride
//   bsel  : EDIM floats                  xs_b[idx_n, :]
//   fxs   : EDIM floats                  sum_q o[q]/u[q] accumulator
//   vlist : FDIM ints                    compacted valid-key indices
//   sints : 2 ints                       [0]=cnt, [1]=idx
#define SMEM_BYTES (FDIM*ROWH*2 + EDIM*4 + EDIM*4 + FDIM*4 + 8)

__global__ __launch_bounds__(NTHREADS, 3)
void model_simple_kernel(const float* __restrict__ X,
                         const float* __restrict__ Xi,
                         const float* __restrict__ Ioh,
                         const float* __restrict__ S,
                         const float* __restrict__ xi_w,
                         const float* __restrict__ xi_b,
                         const float* __restrict__ xs_w,
                         const float* __restrict__ xs_b,
                         float* __restrict__ out)
{
    extern __shared__ float smem[];
    __half* FXh  = (__half*)smem;                    // FDIM*ROWH halves
    float* bsel  = smem + FDIM * ROWH / 2;           // EDIM
    float* fxs   = bsel + EDIM;                      // EDIM
    int*   vlist = (int*)(fxs + EDIM);               // FDIM
    int*   sints = vlist + FDIM;                     // 2

    const int n    = blockIdx.x;
    const int tid  = threadIdx.x;
    const int lane = tid & 31;
    const int wid  = tid >> 5;

    // ---- init + find one-hot index ----
    if (tid < EDIM) fxs[tid] = 0.f;
    for (int f = tid; f < FDIM; f += NTHREADS)
        if (Ioh[(size_t)n * FDIM + f] != 0.f) sints[1] = f;   // exactly one nonzero
    __syncthreads();

    // ---- deterministic compaction of valid keys (warp 0); bsel gather (warp 1) ----
    if (wid == 0) {
        int c = 0;
        for (int base = 0; base < FDIM; base += 32) {
            float sv = S[(size_t)n * FDIM + base + lane];
            unsigned b = __ballot_sync(0xffffffffu, sv != 0.f);
            if (sv != 0.f) vlist[c + __popc(b & ((1u << lane) - 1u))] = base + lane;
            c += __popc(b);
        }
        if (lane == 0) sints[0] = c;
    } else if (wid == 1) {
        bsel[lane] = xs_b[sints[1] * EDIM + lane];
    }
    __syncthreads();

    const int cnt = sints[0];              // >= 1 (S[:,0]=1 guaranteed)
    const int nqt = (cnt + 15) >> 4;       // 16-row tiles (queries AND keys)
    const int nrows = nqt << 4;

    // ---- build compacted FX (fp16): FXh[i][e] = X[n,k_i]*xs_w[k_i,e]+xs_b[k_i,e]+bsel[e] ----
    for (int i = tid; i < cnt; i += NTHREADS) {
        int k = vlist[i];
        float x = X[(size_t)n * FDIM + k];
        const float4* w4 = (const float4*)(xs_w + k * EDIM);
        const float4* b4 = (const float4*)(xs_b + k * EDIM);
        float4* dst = (float4*)(FXh + (size_t)i * ROWH);   // 80 B stride, 16B-aligned
#pragma unroll
        for (int m = 0; m < 4; m++) {
            float4 w0 = w4[2*m],     b0 = b4[2*m];
            float4 w1 = w4[2*m + 1], b1 = b4[2*m + 1];
            float o0 = fmaf(x, w0.x, b0.x) + bsel[m*8 + 0];
            float o1 = fmaf(x, w0.y, b0.y) + bsel[m*8 + 1];
            float o2 = fmaf(x, w0.z, b0.z) + bsel[m*8 + 2];
            float o3 = fmaf(x, w0.w, b0.w) + bsel[m*8 + 3];
            float o4 = fmaf(x, w1.x, b1.x) + bsel[m*8 + 4];
            float o5 = fmaf(x, w1.y, b1.y) + bsel[m*8 + 5];
            float o6 = fmaf(x, w1.z, b1.z) + bsel[m*8 + 6];
            float o7 = fmaf(x, w1.w, b1.w) + bsel[m*8 + 7];
            float4 pk;
            ((__half2*)&pk)[0] = __floats2half2_rn(o0, o1);
            ((__half2*)&pk)[1] = __floats2half2_rn(o2, o3);
            ((__half2*)&pk)[2] = __floats2half2_rn(o4, o5);
            ((__half2*)&pk)[3] = __floats2half2_rn(o6, o7);
            dst[m] = pk;
        }
    }
    // zero-pad tail rows (padded keys masked via A-frag masks; padded queries via inv=0)
    for (int i = cnt + tid; i < nrows; i += NTHREADS) {
        float4* dst = (float4*)(FXh + (size_t)i * ROWH);
#pragma unroll
        for (int m = 0; m < 4; m++) dst[m] = make_float4(0.f, 0.f, 0.f, 0.f);
    }
    __syncthreads();

    const uint32_t smemFX = (uint32_t)__cvta_generic_to_shared(FXh);

    // ldmatrix address components (bytes); FX row stride = 80 B.
    const uint32_t aoff = (uint32_t)(lane & 15) * ROWB + (uint32_t)(lane >> 4) * 16;
    const uint32_t boff = (uint32_t)(lane & 7) * ROWB
                        + (uint32_t)((lane >> 3) & 1) * 16
                        + (uint32_t)(lane >> 4) * (8 * ROWB);
    const uint32_t voff = aoff;   // trans load

    const int gr = lane >> 2;          // row group 0..7
    const int tc = lane & 3;           // col thread 0..3

    // Q pre-scale: fold (1/sqrt(E))*log2(e) into the A-frags once per qtile.
    const __half2 SCH = __float2half2_rn(0.25508329533403174f);
    // Synthesized ones-column B operand for the u-MMA:
    // B[k][n] = (n==0) -> lanes 0-3 hold {1,1} in both b0 (k=2tc,2tc+1) and b1 (k+8,+9).
    const uint32_t bone = (lane < 4) ? 0x3C003C00u : 0u;

    // ---- attention: single pass, warp-private 16-query tiles ----
    for (int qt = wid; qt < nqt; qt += NWARPS) {
        const int q0 = qt << 4;
        uint32_t alo[4], ahi[4];
        {
            uint32_t ad = smemFX + (uint32_t)q0 * ROWB + aoff;
            ldmx4(alo[0], alo[1], alo[2], alo[3], ad);        // e 0-15
            ldmx4(ahi[0], ahi[1], ahi[2], ahi[3], ad + 32);   // e 16-31
#pragma unroll
            for (int i = 0; i < 4; i++) {                     // pre-scale Q
                __half2 t;
                t = __hmul2(*(__half2*)&alo[i], SCH); alo[i] = *(uint32_t*)&t;
                t = __hmul2(*(__half2*)&ahi[i], SCH); ahi[i] = *(uint32_t*)&t;
            }
        }
        float oa[16];
#pragma unroll
        for (int i = 0; i < 16; i++) oa[i] = 0.f;
        float uc0 = 0.f, uc1 = 0.f, uc2 = 0.f, uc3 = 0.f;   // u accumulator (col 0 valid)

        uint32_t bd = smemFX + boff;
        uint32_t vd = smemFX + voff;
        for (int kt = 0; kt < nqt; kt++, bd += 16 * ROWB, vd += 16 * ROWB) {
            const int k0 = kt << 4;
            // ---- load QK B-frags and PV V-frags up front ----
            uint32_t bl[4], bh[4], vl[4], vh[4];
            ldmx4(bl[0], bl[1], bl[2], bl[3], bd);        // e 0-15
            ldmx4(bh[0], bh[1], bh[2], bh[3], bd + 32);   // e 16-31
            ldmx4t(vl[0], vl[1], vl[2], vl[3], vd);       // e 0-15 (trans)
            ldmx4t(vh[0], vh[1], vh[2], vh[3], vd + 32);  // e 16-31 (trans)

            // ---- QK: P[16 x 16], Q pre-scaled so c = s*SCALE*log2(e) ----
            float c0 = 0.f, c1 = 0.f, c2 = 0.f, c3 = 0.f;   // keys k0+0..7
            float d0 = 0.f, d1 = 0.f, d2 = 0.f, d3 = 0.f;   // keys k0+8..15
            mma16816(c0, c1, c2, c3, alo[0], alo[1], alo[2], alo[3], bl[0], bl[1]);
            mma16816(c0, c1, c2, c3, ahi[0], ahi[1], ahi[2], ahi[3], bh[0], bh[1]);
            mma16816(d0, d1, d2, d3, alo[0], alo[1], alo[2], alo[3], bl[2], bl[3]);
            mma16816(d0, d1, d2, d3, ahi[0], ahi[1], ahi[2], ahi[3], bh[2], bh[3]);

            // ---- pack scores to half2, exp in fp16x2 (e = 2^c; scores tiny) ----
            uint32_t A0 = ex2h2(packh2(c0, c1));   // (gr,   keys k0+2tc, +1)
            uint32_t A1 = ex2h2(packh2(c2, c3));   // (gr+8, keys k0+2tc, +1)
            uint32_t A2 = ex2h2(packh2(d0, d1));   // (gr,   keys k0+8+2tc, +1)
            uint32_t A3 = ex2h2(packh2(d2, d3));   // (gr+8, keys k0+8+2tc, +1)

            if (k0 + 16 > cnt) {   // boundary tile only: zero padded-key columns
                const int ka = k0 + 2 * tc;
                __half2 ma = __floats2half2_rn(ka     < cnt ? 1.f : 0.f,
                                               ka + 1 < cnt ? 1.f : 0.f);
                __half2 mb = __floats2half2_rn(ka + 8 < cnt ? 1.f : 0.f,
                                               ka + 9 < cnt ? 1.f : 0.f);
                __half2 t;
                t = __hmul2(*(__half2*)&A0, ma); A0 = *(uint32_t*)&t;
                t = __hmul2(*(__half2*)&A1, ma); A1 = *(uint32_t*)&t;
                t = __hmul2(*(__half2*)&A2, mb); A2 = *(uint32_t*)&t;
                t = __hmul2(*(__half2*)&A3, mb); A3 = *(uint32_t*)&t;
            }

            // ---- PV: O[16 x 32] += P * FX[k0:k0+16, :]; u via ones-column MMA ----
            mma16816(oa[0],  oa[1],  oa[2],  oa[3],  A0, A1, A2, A3, vl[0], vl[1]); // e0-7
            mma16816(oa[4],  oa[5],  oa[6],  oa[7],  A0, A1, A2, A3, vl[2], vl[3]); // e8-15
            mma16816(oa[8],  oa[9],  oa[10], oa[11], A0, A1, A2, A3, vh[0], vh[1]); // e16-23
            mma16816(oa[12], oa[13], oa[14], oa[15], A0, A1, A2, A3, vh[2], vh[3]); // e24-31
            mma16816(uc0, uc1, uc2, uc3, A0, A1, A2, A3, bone, bone);               // u (col 0)
        }

        // u for rows gr / gr+8 sits in col 0 (tc==0 lanes): broadcast within row group
        float u0 = __shfl_sync(0xffffffffu, uc0, lane & ~3);
        float u1 = __shfl_sync(0xffffffffu, uc2, lane & ~3);
        const float inv0 = (q0 + gr     < cnt) ? 1.f / u0 : 0.f;  // u>0 for valid rows
        const float inv1 = (q0 + gr + 8 < cnt) ? 1.f / u1 : 0.f;

        // normalize, reduce over rows, accumulate into fxs
#pragma unroll
        for (int j = 0; j < 4; j++) {
            float s0 = oa[4*j + 0] * inv0 + oa[4*j + 2] * inv1;  // col 8j + 2tc
            float s1 = oa[4*j + 1] * inv0 + oa[4*j + 3] * inv1;  // col 8j + 2tc + 1
            s0 += __shfl_xor_sync(0xffffffffu, s0, 4);
            s0 += __shfl_xor_sync(0xffffffffu, s0, 8);
            s0 += __shfl_xor_sync(0xffffffffu, s0, 16);
            s1 += __shfl_xor_sync(0xffffffffu, s1, 4);
            s1 += __shfl_xor_sync(0xffffffffu, s1, 8);
            s1 += __shfl_xor_sync(0xffffffffu, s1, 16);
            if (lane < 4) {
                atomicAdd(&fxs[8*j + 2*lane],     s0);
                atomicAdd(&fxs[8*j + 2*lane + 1], s1);
            }
        }
    }
    __syncthreads();

    // ---- epilogue (warp 0) ----
    if (wid == 0) {
        int idx = sints[1];
        float f  = fxs[lane] / (float)cnt;
        float iw = xi_w[idx * EDIM + lane];
        float ib = xi_b[idx * EDIM + lane];
        float t0 = warpSum(ib * f);           // Xi = 0 branch
        float t1 = warpSum((iw + ib) * f);    // Xi = 1 branch
        if (lane == 0) {
            float xi = Xi[n];
            float ul = t0 + xi * (t1 - t0);   // sum(Fxi * Fxs)
            float M  = fmaxf(t0, t1);
            float lz = M + logf(ex2(1.442695041f * (t0 - M)) + ex2(1.442695041f * (t1 - M)));
            out[n] = ul - lz;
        }
    }
}

extern "C" void kernel_launch(void* const* d_in, const int* in_sizes, int n_in,
                              void* d_out, int out_size)
{
    const float* X    = (const float*)d_in[0];
    const float* Xi   = (const float*)d_in[1];
    const float* Ioh  = (const float*)d_in[2];
    const float* S    = (const float*)d_in[3];
    const float* xi_w = (const float*)d_in[4];
    const float* xi_b = (const float*)d_in[5];
    const float* xs_w = (const float*)d_in[6];
    const float* xs_b = (const float*)d_in[7];
    float* out = (float*)d_out;

    const int N = in_sizes[1];  // Xi length = batch

    // Unconditional (no static guard): non-stream host API, capture-safe, idempotent.
    cudaFuncSetAttribute(model_simple_kernel,
                         cudaFuncAttributeMaxDynamicSharedMemorySize, SMEM_BYTES);

    model_simple_kernel<<<N, NTHREADS, SMEM_BYTES>>>(
        X, Xi, Ioh, S, xi_w, xi_b, xs_w, xs_b, out);
}

// round 15
// speedup vs baseline: 1.5611x; 1.5611x over previous
#include <cuda_runtime.h>
#include <cuda_fp16.h>
#include <cstdint>

// Problem constants (fixed shapes: N=2048, F=512, E=32)
#define FDIM 512
#define EDIM 32
#define NWARPS 8
#define NTHREADS (NWARPS * 32)
#define ROWH 40   // halves per FX row (80 B). 8-row ldmatrix groups span all 32 banks.
#define ROWB (ROWH * 2)

__device__ __forceinline__ float warpSum(float v) {
#pragma unroll
    for (int o = 16; o; o >>= 1) v += __shfl_xor_sync(0xffffffffu, v, o);
    return v;
}
__device__ __forceinline__ float ex2(float x) {   // 2^x
    float r;
    asm("ex2.approx.ftz.f32 %0, %1;" : "=f"(r) : "f"(x));
    return r;
}

__device__ __forceinline__ void ldmx4(uint32_t& r0, uint32_t& r1, uint32_t& r2, uint32_t& r3,
                                      uint32_t addr) {
    asm volatile("ldmatrix.sync.aligned.m8n8.x4.shared.b16 {%0,%1,%2,%3}, [%4];"
                 : "=r"(r0), "=r"(r1), "=r"(r2), "=r"(r3) : "r"(addr));
}
__device__ __forceinline__ void ldmx4t(uint32_t& r0, uint32_t& r1, uint32_t& r2, uint32_t& r3,
                                       uint32_t addr) {
    asm volatile("ldmatrix.sync.aligned.m8n8.x4.trans.shared.b16 {%0,%1,%2,%3}, [%4];"
                 : "=r"(r0), "=r"(r1), "=r"(r2), "=r"(r3) : "r"(addr));
}
__device__ __forceinline__ void mma16816(float& d0, float& d1, float& d2, float& d3,
                                         uint32_t a0, uint32_t a1, uint32_t a2, uint32_t a3,
                                         uint32_t b0, uint32_t b1) {
    asm volatile("mma.sync.aligned.m16n8k16.row.col.f32.f16.f16.f32 "
                 "{%0,%1,%2,%3},{%4,%5,%6,%7},{%8,%9},{%0,%1,%2,%3};"
                 : "+f"(d0), "+f"(d1), "+f"(d2), "+f"(d3)
                 : "r"(a0), "r"(a1), "r"(a2), "r"(a3), "r"(b0), "r"(b1));
}

// Shared layout:
//   FXh   : FDIM*ROWH halves = 40960 B   compacted FX (fp16), 40-half row stride
//   bsel  : EDIM floats                  xs_b[idx_n, :]
//   fxs   : EDIM floats                  sum_q o[q]/u[q] accumulator
//   vlist : FDIM ints                    compacted valid-key indices
//   sints : 2 ints                       [0]=cnt, [1]=idx
//   pad   : 1280 B                       guard so last-iter B-prefetch stays in-bounds
#define SMEM_BYTES (FDIM*ROWH*2 + EDIM*4 + EDIM*4 + FDIM*4 + 8 + 1280)

__global__ __launch_bounds__(NTHREADS, 3)
void model_simple_kernel(const float* __restrict__ X,
                         const float* __restrict__ Xi,
                         const float* __restrict__ Ioh,
                         const float* __restrict__ S,
                         const float* __restrict__ xi_w,
                         const float* __restrict__ xi_b,
                         const float* __restrict__ xs_w,
                         const float* __restrict__ xs_b,
                         float* __restrict__ out)
{
    extern __shared__ float smem[];
    __half* FXh  = (__half*)smem;                    // FDIM*ROWH halves
    float* bsel  = smem + FDIM * ROWH / 2;           // EDIM
    float* fxs   = bsel + EDIM;                      // EDIM
    int*   vlist = (int*)(fxs + EDIM);               // FDIM
    int*   sints = vlist + FDIM;                     // 2

    const int n    = blockIdx.x;
    const int tid  = threadIdx.x;
    const int lane = tid & 31;
    const int wid  = tid >> 5;

    // ---- init + find one-hot index ----
    if (tid < EDIM) fxs[tid] = 0.f;
    for (int f = tid; f < FDIM; f += NTHREADS)
        if (Ioh[(size_t)n * FDIM + f] != 0.f) sints[1] = f;   // exactly one nonzero
    __syncthreads();

    // ---- deterministic compaction of valid keys (warp 0); bsel gather (warp 1) ----
    if (wid == 0) {
        int c = 0;
        for (int base = 0; base < FDIM; base += 32) {
            float sv = S[(size_t)n * FDIM + base + lane];
            unsigned b = __ballot_sync(0xffffffffu, sv != 0.f);
            if (sv != 0.f) vlist[c + __popc(b & ((1u << lane) - 1u))] = base + lane;
            c += __popc(b);
        }
        if (lane == 0) sints[0] = c;
    } else if (wid == 1) {
        bsel[lane] = xs_b[sints[1] * EDIM + lane];
    }
    __syncthreads();

    const int cnt = sints[0];              // >= 1 (S[:,0]=1 guaranteed)
    const int nqt = (cnt + 15) >> 4;       // 16-row tiles (queries AND keys)
    const int nrows = nqt << 4;

    // ---- build compacted FX (fp16): FXh[i][e] = X[n,k_i]*xs_w[k_i,e]+xs_b[k_i,e]+bsel[e] ----
    for (int i = tid; i < cnt; i += NTHREADS) {
        int k = vlist[i];
        float x = X[(size_t)n * FDIM + k];
        const float4* w4 = (const float4*)(xs_w + k * EDIM);
        const float4* b4 = (const float4*)(xs_b + k * EDIM);
        float4* dst = (float4*)(FXh + (size_t)i * ROWH);   // 80 B stride, 16B-aligned
#pragma unroll
        for (int m = 0; m < 4; m++) {
            float4 w0 = w4[2*m],     b0 = b4[2*m];
            float4 w1 = w4[2*m + 1], b1 = b4[2*m + 1];
            float o0 = fmaf(x, w0.x, b0.x) + bsel[m*8 + 0];
            float o1 = fmaf(x, w0.y, b0.y) + bsel[m*8 + 1];
            float o2 = fmaf(x, w0.z, b0.z) + bsel[m*8 + 2];
            float o3 = fmaf(x, w0.w, b0.w) + bsel[m*8 + 3];
            float o4 = fmaf(x, w1.x, b1.x) + bsel[m*8 + 4];
            float o5 = fmaf(x, w1.y, b1.y) + bsel[m*8 + 5];
            float o6 = fmaf(x, w1.z, b1.z) + bsel[m*8 + 6];
            float o7 = fmaf(x, w1.w, b1.w) + bsel[m*8 + 7];
            float4 pk;
            ((__half2*)&pk)[0] = __floats2half2_rn(o0, o1);
            ((__half2*)&pk)[1] = __floats2half2_rn(o2, o3);
            ((__half2*)&pk)[2] = __floats2half2_rn(o4, o5);
            ((__half2*)&pk)[3] = __floats2half2_rn(o6, o7);
            dst[m] = pk;
        }
    }
    // zero-pad tail rows (padded keys masked to e=0; padded queries die via inv=0)
    for (int i = cnt + tid; i < nrows; i += NTHREADS) {
        float4* dst = (float4*)(FXh + (size_t)i * ROWH);
#pragma unroll
        for (int m = 0; m < 4; m++) dst[m] = make_float4(0.f, 0.f, 0.f, 0.f);
    }
    __syncthreads();

    const uint32_t smemFX = (uint32_t)__cvta_generic_to_shared(FXh);

    // ldmatrix address components (bytes); FX row stride = 80 B.
    const uint32_t aoff = (uint32_t)(lane & 15) * ROWB + (uint32_t)(lane >> 4) * 16;
    const uint32_t boff = (uint32_t)(lane & 7) * ROWB
                        + (uint32_t)((lane >> 3) & 1) * 16
                        + (uint32_t)(lane >> 4) * (8 * ROWB);
    const uint32_t voff = aoff;   // trans load

    const int gr = lane >> 2;          // row group 0..7
    const int tc = lane & 3;           // col thread 0..3

    // Q pre-scale: fold (1/sqrt(E))*log2(e) into the A-frags once per qtile,
    // so e = ex2(c) directly (no per-score FMUL on the critical path).
    const __half2 SCH = __float2half2_rn(0.25508329533403174f);

    // ---- attention: single pass, warp-private 16-query tiles,
    //      QK B-frags software-pipelined one ktile ahead ----
    for (int qt = wid; qt < nqt; qt += NWARPS) {
        const int q0 = qt << 4;
        uint32_t alo[4], ahi[4];
        {
            uint32_t ad = smemFX + (uint32_t)q0 * ROWB + aoff;
            ldmx4(alo[0], alo[1], alo[2], alo[3], ad);        // e 0-15
            ldmx4(ahi[0], ahi[1], ahi[2], ahi[3], ad + 32);   // e 16-31
#pragma unroll
            for (int i = 0; i < 4; i++) {                     // pre-scale Q (fp16)
                __half2 t;
                t = __hmul2(*(__half2*)&alo[i], SCH); alo[i] = *(uint32_t*)&t;
                t = __hmul2(*(__half2*)&ahi[i], SCH); ahi[i] = *(uint32_t*)&t;
            }
        }
        float oa[16];
#pragma unroll
        for (int i = 0; i < 16; i++) oa[i] = 0.f;
        float u0 = 0.f, u1 = 0.f;

        uint32_t bd = smemFX + boff;
        uint32_t vd = smemFX + voff;
        uint32_t bl[4], bh[4];
        ldmx4(bl[0], bl[1], bl[2], bl[3], bd);        // prologue: B-frags of kt=0
        ldmx4(bh[0], bh[1], bh[2], bh[3], bd + 32);

        for (int kt = 0; kt < nqt; kt++) {
            const int k0 = kt << 4;
            // ---- V frags for current ktile (consumed ~20 slots later) ----
            uint32_t vl[4], vh[4];
            ldmx4t(vl[0], vl[1], vl[2], vl[3], vd);       // e 0-15 (trans)
            ldmx4t(vh[0], vh[1], vh[2], vh[3], vd + 32);  // e 16-31 (trans)
            vd += 16 * ROWB;

            // ---- QK: P[16 x 16] using PREFETCHED frags (no head-of-iter stall) ----
            float c0 = 0.f, c1 = 0.f, c2 = 0.f, c3 = 0.f;   // keys k0+0..7
            float d0 = 0.f, d1 = 0.f, d2 = 0.f, d3 = 0.f;   // keys k0+8..15
            mma16816(c0, c1, c2, c3, alo[0], alo[1], alo[2], alo[3], bl[0], bl[1]);
            mma16816(c0, c1, c2, c3, ahi[0], ahi[1], ahi[2], ahi[3], bh[0], bh[1]);
            mma16816(d0, d1, d2, d3, alo[0], alo[1], alo[2], alo[3], bl[2], bl[3]);
            mma16816(d0, d1, d2, d3, ahi[0], ahi[1], ahi[2], ahi[3], bh[2], bh[3]);

            // ---- prefetch NEXT ktile's B-frags (full iteration of slack;
            //      last iter reads in-bounds scratch, result unused) ----
            uint32_t nbl[4], nbh[4];
            bd += 16 * ROWB;
            ldmx4(nbl[0], nbl[1], nbl[2], nbl[3], bd);
            ldmx4(nbh[0], nbh[1], nbh[2], nbh[3], bd + 32);

            // ---- exp (Q pre-scaled: e = 2^c); masks only in the boundary tile ----
            float ec0, ec1, ec2, ec3, ed0, ed1, ed2, ed3;
            if (k0 + 16 <= cnt) {   // full tile (uniform branch): mask-free
                ec0 = ex2(c0); ec1 = ex2(c1); ec2 = ex2(c2); ec3 = ex2(c3);
                ed0 = ex2(d0); ed1 = ex2(d1); ed2 = ex2(d2); ed3 = ex2(d3);
            } else {
                const int ka = k0 + 2 * tc, kb = ka + 8;
                ec0 = (ka     < cnt) ? ex2(c0) : 0.f;
                ec1 = (ka + 1 < cnt) ? ex2(c1) : 0.f;
                ec2 = (ka     < cnt) ? ex2(c2) : 0.f;
                ec3 = (ka + 1 < cnt) ? ex2(c3) : 0.f;
                ed0 = (kb     < cnt) ? ex2(d0) : 0.f;
                ed1 = (kb + 1 < cnt) ? ex2(d1) : 0.f;
                ed2 = (kb     < cnt) ? ex2(d2) : 0.f;
                ed3 = (kb + 1 < cnt) ? ex2(d3) : 0.f;
            }
            u0 += (ec0 + ec1) + (ed0 + ed1);
            u1 += (ec2 + ec3) + (ed2 + ed3);

            // ---- pack P to fp16 A-frags (C-frag -> A-frag identity) ----
            __half2 h0 = __floats2half2_rn(ec0, ec1);   // (gr,   keys k0+2tc, +1)
            __half2 h1 = __floats2half2_rn(ec2, ec3);   // (gr+8, keys k0+2tc, +1)
            __half2 h2 = __floats2half2_rn(ed0, ed1);   // (gr,   keys k0+8+2tc, +1)
            __half2 h3 = __floats2half2_rn(ed2, ed3);   // (gr+8, keys k0+8+2tc, +1)
            uint32_t A0 = *(uint32_t*)&h0;
            uint32_t A1 = *(uint32_t*)&h1;
            uint32_t A2 = *(uint32_t*)&h2;
            uint32_t A3 = *(uint32_t*)&h3;

            // ---- PV: O[16 x 32] += P * FX[k0:k0+16, :] ----
            mma16816(oa[0],  oa[1],  oa[2],  oa[3],  A0, A1, A2, A3, vl[0], vl[1]); // e0-7
            mma16816(oa[4],  oa[5],  oa[6],  oa[7],  A0, A1, A2, A3, vl[2], vl[3]); // e8-15
            mma16816(oa[8],  oa[9],  oa[10], oa[11], A0, A1, A2, A3, vh[0], vh[1]); // e16-23
            mma16816(oa[12], oa[13], oa[14], oa[15], A0, A1, A2, A3, vh[2], vh[3]); // e24-31

            // ---- rotate prefetched frags into place ----
#pragma unroll
            for (int i = 0; i < 4; i++) { bl[i] = nbl[i]; bh[i] = nbh[i]; }
        }

        // row sums: reduce over the 4 col-threads
        u0 += __shfl_xor_sync(0xffffffffu, u0, 1);
        u0 += __shfl_xor_sync(0xffffffffu, u0, 2);
        u1 += __shfl_xor_sync(0xffffffffu, u1, 1);
        u1 += __shfl_xor_sync(0xffffffffu, u1, 2);
        const float inv0 = (q0 + gr     < cnt) ? 1.f / u0 : 0.f;  // u>0 for valid rows
        const float inv1 = (q0 + gr + 8 < cnt) ? 1.f / u1 : 0.f;

        // normalize, reduce over rows, accumulate into fxs
#pragma unroll
        for (int j = 0; j < 4; j++) {
            float s0 = oa[4*j + 0] * inv0 + oa[4*j + 2] * inv1;  // col 8j + 2tc
            float s1 = oa[4*j + 1] * inv0 + oa[4*j + 3] * inv1;  // col 8j + 2tc + 1
            s0 += __shfl_xor_sync(0xffffffffu, s0, 4);
            s0 += __shfl_xor_sync(0xffffffffu, s0, 8);
            s0 += __shfl_xor_sync(0xffffffffu, s0, 16);
            s1 += __shfl_xor_sync(0xffffffffu, s1, 4);
            s1 += __shfl_xor_sync(0xffffffffu, s1, 8);
            s1 += __shfl_xor_sync(0xffffffffu, s1, 16);
            if (lane < 4) {
                atomicAdd(&fxs[8*j + 2*lane],     s0);
                atomicAdd(&fxs[8*j + 2*lane + 1], s1);
            }
        }
    }
    __syncthreads();

    // ---- epilogue (warp 0) ----
    if (wid == 0) {
        int idx = sints[1];
        float f  = fxs[lane] / (float)cnt;
        float iw = xi_w[idx * EDIM + lane];
        float ib = xi_b[idx * EDIM + lane];
        float t0 = warpSum(ib * f);           // Xi = 0 branch
        float t1 = warpSum((iw + ib) * f);    // Xi = 1 branch
        if (lane == 0) {
            float xi = Xi[n];
            float ul = t0 + xi * (t1 - t0);   // sum(Fxi * Fxs)
            float M  = fmaxf(t0, t1);
            float lz = M + logf(__expf(t0 - M) + __expf(t1 - M));
            out[n] = ul - lz;
        }
    }
}

extern "C" void kernel_launch(void* const* d_in, const int* in_sizes, int n_in,
                              void* d_out, int out_size)
{
    const float* X    = (const float*)d_in[0];
    const float* Xi   = (const float*)d_in[1];
    const float* Ioh  = (const float*)d_in[2];
    const float* S    = (const float*)d_in[3];
    const float* xi_w = (const float*)d_in[4];
    const float* xi_b = (const float*)d_in[5];
    const float* xs_w = (const float*)d_in[6];
    const float* xs_b = (const float*)d_in[7];
    float* out = (float*)d_out;

    const int N = in_sizes[1];  // Xi length = batch

    // Unconditional (no static guard): non-stream host API, capture-safe, idempotent.
    cudaFuncSetAttribute(model_simple_kernel,
                         cudaFuncAttributeMaxDynamicSharedMemorySize, SMEM_BYTES);

    model_simple_kernel<<<N, NTHREADS, SMEM_BYTES>>>(
        X, Xi, Ioh, S, xi_w, xi_b, xs_w, xs_b, out);
}